// round 11
// baseline (speedup 1.0000x reference)
#include <cuda_runtime.h>
#include <math.h>
#include <stdint.h>

// ---------------- problem constants (fixed shapes) ----------------
#define BB    64      // batch
#define NBLK  128     // persistent blocks; block i owns hidden dims [4i,4i+4)
#define NTHR  1024
#define KTOT  1024    // GEMM K = D + H
#define WST   1032    // SMEM weight row stride (1024 + 8 pad)
#define NKSL  8       // k-slices (128 k each)
#define RST   68      // red row stride (64 + 4)
#define RSL   1088    // red slice stride (16 rows * 68)
#define ATTN_THRESH 1e-10f

// ---------------- SMEM layout (float offsets) ----------------
#define OFF_W     0
#define SZ_W      (16*WST)              // 16512
#define OFF_RED   (OFF_W + SZ_W)
#define SZ_RED    (NKSL*RSL)            // 8704
#define OFF_ATTNA (OFF_RED + SZ_RED)
#define OFF_ATTNB (OFF_ATTNA + 1024)
#define OFF_GATES (OFF_ATTNB + 1024)    // 16 rows x 64 b
#define OFF_C     (OFF_GATES + 1024)    // 256
#define OFF_H2    (OFF_C + 256)         // 256
#define OFF_BS    (OFF_H2 + 256)        // 16
#define OFF_WSP   (OFF_BS + 16)         // 8
#define OFF_BSP   (OFF_WSP + 8)         // 2
#define OFF_SCR   (OFF_BSP + 2)         // 40 reduce scratch
#define OFF_WIN   (OFF_SCR + 40)        // 2 ints
#define SMEM_FLOATS (OFF_WIN + 4)
#define SMEM_BYTES  (SMEM_FLOATS*4)

// ---------------- persistent global state ----------------
// g_AT2: k-pair interleaved activations: (k,b) at (k>>1)*128 + b*2 + (k&1)
// k < 512 -> time_in rows, k >= 512 -> h rows.
__device__ __align__(16) float g_AT2[KTOT * BB];
__device__ float    g_spp[BB * 256];     // sp partials, batch-major [b][g*128+blk]
__device__ unsigned g_cnt;               // flat barrier count (returns to 0)
__device__ unsigned g_gen;               // barrier generation (monotone)

// ---------------- f32x2 helpers ----------------
__device__ __forceinline__ void fma2(unsigned long long &d,
                                     unsigned long long a, unsigned long long b) {
    asm("fma.rn.f32x2 %0, %1, %2, %0;" : "+l"(d) : "l"(a), "l"(b));
}
__device__ __forceinline__ void split2(float4 w, unsigned long long &lo,
                                       unsigned long long &hi) {
    asm("mov.b64 %0, {%2, %3};\n\tmov.b64 %1, {%4, %5};"
        : "=l"(lo), "=l"(hi) : "f"(w.x), "f"(w.y), "f"(w.z), "f"(w.w));
}
__device__ __forceinline__ float hsum2(unsigned long long v) {
    float lo, hi;
    asm("mov.b64 {%0, %1}, %2;" : "=f"(lo), "=f"(hi) : "l"(v));
    return lo + hi;
}

// ---------------- flat grid-wide barrier (all 128 blocks co-resident) --------
// Full release fence before arrival; acquire fence after release (also
// invalidates L1 so fresh cross-SM data is re-fetched; intra-phase reuse
// still hits L1).
__device__ __forceinline__ void grid_barrier() {
    __syncthreads();
    __threadfence();
    if (threadIdx.x == 0) {
        unsigned gen = *(volatile unsigned*)&g_gen;
        if (atomicAdd(&g_cnt, 1u) == gridDim.x - 1) {
            atomicExch(&g_cnt, 0u);
            __threadfence();
            atomicExch(&g_gen, gen + 1u);
        } else {
            while (*(volatile unsigned*)&g_gen == gen) { __nanosleep(32); }
        }
    }
    __syncthreads();
    __threadfence();   // acquire + L1 invalidate
}

// ---------------- block reductions (1024 thr = 32 warps) ----------------
__device__ __forceinline__ float brsum(float v, float* scr) {
#pragma unroll
    for (int o = 16; o; o >>= 1) v += __shfl_xor_sync(0xffffffffu, v, o);
    __syncthreads();
    if ((threadIdx.x & 31) == 0) scr[threadIdx.x >> 5] = v;
    __syncthreads();
    if (threadIdx.x < 32) {
        float w = scr[threadIdx.x];
#pragma unroll
        for (int o = 16; o; o >>= 1) w += __shfl_xor_sync(0xffffffffu, w, o);
        if (threadIdx.x == 0) scr[0] = w;
    }
    __syncthreads();
    return scr[0];
}
__device__ __forceinline__ float brmax(float v, float* scr) {
#pragma unroll
    for (int o = 16; o; o >>= 1) v = fmaxf(v, __shfl_xor_sync(0xffffffffu, v, o));
    __syncthreads();
    if ((threadIdx.x & 31) == 0) scr[threadIdx.x >> 5] = v;
    __syncthreads();
    if (threadIdx.x < 32) {
        float w = scr[threadIdx.x];
#pragma unroll
        for (int o = 16; o; o >>= 1) w = fmaxf(w, __shfl_xor_sync(0xffffffffu, w, o));
        if (threadIdx.x == 0) scr[0] = w;
    }
    __syncthreads();
    return scr[0];
}

// ---------------- time_in over attn window; writes g_AT2 tin rows ------------
__device__ __forceinline__ void compute_tin(const float* __restrict__ input,
                                            const float* __restrict__ an,
                                            float* tinred, int b, int dstart,
                                            int lo, int hi, int tid) {
    __syncthreads();
    const int dloc = tid & 255;
    const int ls   = tid >> 8;       // 0..3
    float s = 0.f;
    const float* xp = input + (size_t)b * 512 + dstart + dloc;
    for (int l = lo + ls; l <= hi; l += 4)
        s = fmaf(xp[(size_t)l * 32768], an[l], s);
    tinred[ls * 256 + dloc] = s;
    __syncthreads();
    if (tid < 256) {
        float v = tinred[tid] + tinred[256 + tid] + tinred[512 + tid] + tinred[768 + tid];
        const int k = dstart + tid;
        g_AT2[(k >> 1) * 128 + b * 2 + (k & 1)] = v;
    }
}

// ---------------- persistent kernel ----------------
__global__ void __launch_bounds__(NTHR, 1)
spacing_rnn_kernel(const float* __restrict__ input, const int* __restrict__ plen,
                   const float* __restrict__ Wih, const float* __restrict__ Whh,
                   const float* __restrict__ bih, const float* __restrict__ bhh,
                   const float* __restrict__ Wsp, const float* __restrict__ bsp,
                   float* __restrict__ out, int L)
{
    extern __shared__ float sm[];
    float* Wsm   = sm + OFF_W;
    float* red   = sm + OFF_RED;
    float* attnA = sm + OFF_ATTNA;
    float* attnB = sm + OFF_ATTNB;
    float* gates = sm + OFF_GATES;
    float* csm   = sm + OFF_C;
    float* h2s   = sm + OFF_H2;
    float* bsum  = sm + OFF_BS;
    float* wspc  = sm + OFF_WSP;
    float* bspc  = sm + OFF_BSP;
    float* scr   = sm + OFF_SCR;
    int*   win   = (int*)(sm + OFF_WIN);

    const int tid    = threadIdx.x;
    const int bi     = blockIdx.x;
    const int j0     = bi * 4;              // owned hidden dims j0..j0+3
    const int b      = bi & 63;             // phase-B batch served by this block
    const int dstart = (bi >> 6) * 256;
    int len = plen[0];
    if (len <= 0 || len > L) len = L;

    // ---------------- prologue ----------------
    for (int li = tid; li < 16 * 1024; li += NTHR) {
        int r = li >> 10, k = li & 1023;
        int gate = r >> 2, jl = r & 3;
        int grow = gate * 512 + j0 + jl;
        float w = (k < 512) ? Wih[grow * 512 + k] : Whh[grow * 512 + k - 512];
        Wsm[r * WST + k] = w;
    }
    if (tid < 16) {
        int gate = tid >> 2, jl = tid & 3;
        int grow = gate * 512 + j0 + jl;
        bsum[tid] = bih[grow] + bhh[grow];
    }
    if (tid < 8)  wspc[tid] = Wsp[(tid >> 2) * 512 + j0 + (tid & 3)];
    if (tid < 2)  bspc[tid] = bsp[tid];
    attnA[tid] = (tid == 0) ? 1.f : 0.f;
    attnB[tid] = 0.f;
    if (tid < 256) {
        csm[tid] = 0.f;
        const int k = 512 + j0 + (tid & 3);
        g_AT2[(k >> 1) * 128 + (tid >> 2) * 2 + (k & 1)] = 0.f;   // h0 = 0
    }
    __syncthreads();
    compute_tin(input, attnA, red, b, dstart, 0, 0, tid);   // tin(0) = x[:, :, 0]
    grid_barrier();

    float* cur = attnA;
    float* nxt = attnB;
    int sup = 0;

    for (int t = 0; t < len; t++) {
        // ============ PHASE A: gates GEMM (f32x2, 4b x 2r x 128k) ============
        {
            const int tile = tid & 127;       // 128 tiles
            const int ks   = tid >> 7;        // 8 k-slices
            const int bt   = tile & 15;       // b-tile (4 b)
            const int rt   = tile >> 4;       // r-tile (2 rows)
            const int b0   = bt * 4;
            const int r0   = rt * 2;
            const int k0   = ks * 128;
            unsigned long long acc[2][4];
#pragma unroll
            for (int j = 0; j < 2; j++)
#pragma unroll
                for (int i = 0; i < 4; i++) acc[j][i] = 0ull;
            const float* Wb = Wsm + r0 * WST;
#pragma unroll 4
            for (int kk = 0; kk < 128; kk += 4) {
                const int k = k0 + kk;
                float4 w0f = *(const float4*)(Wb + k);
                float4 w1f = *(const float4*)(Wb + WST + k);
                const float* pa = g_AT2 + (size_t)(k >> 1) * 128 + b0 * 2;
                ulonglong2 A01 = *(const ulonglong2*)(pa);        // b0,b1 @ (k,k+1)
                ulonglong2 A23 = *(const ulonglong2*)(pa + 4);    // b2,b3 @ (k,k+1)
                ulonglong2 B01 = *(const ulonglong2*)(pa + 128);  // b0,b1 @ (k+2,k+3)
                ulonglong2 B23 = *(const ulonglong2*)(pa + 132);
                unsigned long long wl0, wh0, wl1, wh1;
                split2(w0f, wl0, wh0); split2(w1f, wl1, wh1);
                fma2(acc[0][0], A01.x, wl0); fma2(acc[0][1], A01.y, wl0);
                fma2(acc[0][2], A23.x, wl0); fma2(acc[0][3], A23.y, wl0);
                fma2(acc[1][0], A01.x, wl1); fma2(acc[1][1], A01.y, wl1);
                fma2(acc[1][2], A23.x, wl1); fma2(acc[1][3], A23.y, wl1);
                fma2(acc[0][0], B01.x, wh0); fma2(acc[0][1], B01.y, wh0);
                fma2(acc[0][2], B23.x, wh0); fma2(acc[0][3], B23.y, wh0);
                fma2(acc[1][0], B01.x, wh1); fma2(acc[1][1], B01.y, wh1);
                fma2(acc[1][2], B23.x, wh1); fma2(acc[1][3], B23.y, wh1);
            }
            const int base = ks * RSL + r0 * RST + b0;
            float4 v0, v1;
            v0.x = hsum2(acc[0][0]); v0.y = hsum2(acc[0][1]);
            v0.z = hsum2(acc[0][2]); v0.w = hsum2(acc[0][3]);
            v1.x = hsum2(acc[1][0]); v1.y = hsum2(acc[1][1]);
            v1.z = hsum2(acc[1][2]); v1.w = hsum2(acc[1][3]);
            *(float4*)(red + base)       = v0;
            *(float4*)(red + base + RST) = v1;
        }
        __syncthreads();
        {   // gather 8 k-slice partials -> gates[r][b]
            const int r = tid >> 6, bb2 = tid & 63;
            float s = 0.f;
#pragma unroll
            for (int ks2 = 0; ks2 < NKSL; ks2++) s += red[ks2 * RSL + r * RST + bb2];
            gates[r * 64 + bb2] = s;
        }
        __syncthreads();
        if (tid < 256) {  // LSTM cell for (b = tid>>2, jl = tid&3)
            const int bb2 = tid >> 2, jl = tid & 3;
            float gi = gates[(0  + jl) * 64 + bb2] + bsum[0  + jl];
            float gf = gates[(4  + jl) * 64 + bb2] + bsum[4  + jl];
            float gg = gates[(8  + jl) * 64 + bb2] + bsum[8  + jl];
            float go = gates[(12 + jl) * 64 + bb2] + bsum[12 + jl];
            float c  = csm[tid];
            float si = 1.f / (1.f + __expf(-gi));
            float sf = 1.f / (1.f + __expf(-gf));
            float so = 1.f / (1.f + __expf(-go));
            float c2 = sf * c + si * tanhf(gg);
            float h2 = so * tanhf(c2);
            csm[tid] = c2;
            h2s[tid] = h2;
            out[(size_t)t * 32768 + (size_t)bb2 * 512 + j0 + jl] = h2;
        }
        __syncthreads();
        if (tid < 128) {  // sp partial (batch-major store for contiguous reload)
            const int g = tid >> 6, bb2 = tid & 63;
            float s = h2s[bb2 * 4 + 0] * wspc[g * 4 + 0] + h2s[bb2 * 4 + 1] * wspc[g * 4 + 1]
                    + h2s[bb2 * 4 + 2] * wspc[g * 4 + 2] + h2s[bb2 * 4 + 3] * wspc[g * 4 + 3];
            g_spp[bb2 * 256 + g * 128 + bi] = s;
        }
        grid_barrier();  // h(t-1) reads done; sp partials visible

        // ============ PHASE B: publish h, attn update, time_in ============
        if (t + 1 < len) {
            if (tid < 256) {  // publish h2 -> g_AT2 (all GEMM reads done)
                const int bb2 = tid >> 2, jl = tid & 3;
                const int k = 512 + j0 + jl;
                g_AT2[(k >> 1) * 128 + bb2 * 2 + (k & 1)] = h2s[tid];
            }
            // --- reduce sp over 128 blocks for batch b (contiguous read) ---
            {
                float v = (tid < 256) ? g_spp[b * 256 + tid] : 0.f;
#pragma unroll
                for (int o = 16; o; o >>= 1) v += __shfl_xor_sync(0xffffffffu, v, o);
                if (tid < 256 && (tid & 31) == 0) scr[32 + (tid >> 5)] = v;  // 8 partials
                __syncthreads();
                if (tid == 0) {
                    float sp0 = scr[32] + scr[33] + scr[34] + scr[35];
                    float sp1 = scr[36] + scr[37] + scr[38] + scr[39];
                    scr[30] = 1.f / (1.f + __expf(-(sp0 + bspc[0])));
                    float pp = sp1 + bspc[1];
                    scr[31] = (pp > 0.f ? pp : 0.f) + 1.f;
                }
                __syncthreads();
            }
            const float shift = scr[30];
            const float p     = scr[31];
            const int sup2 = min(sup + 1, L - 1);
            __syncthreads();
            if (tid == 0) { win[0] = 0x7fffffff; win[1] = -1; }
            // --- attn: shift mix (exact, full support), 1 elem per thread ---
            float a2 = 0.f;
            if (tid <= sup2) {
                float a  = cur[tid];
                float ap = (tid > 0) ? cur[tid - 1] : 0.f;
                a2 = (1.f - shift) * a + shift * ap;
            }
            // --- sharpen + normalize (max-scaled pow; identical after normalize) ---
            float amax  = brmax(a2, scr);
            float lmax  = __logf(amax);
            float powed = (a2 > 0.f) ? __expf(p * (__logf(a2) - lmax)) : 0.f;
            float ssum  = brsum(powed, scr);
            float anew  = powed * (1.f / ssum);
            nxt[tid] = anew;
            if (anew >= ATTN_THRESH) { atomicMin(&win[0], tid); atomicMax(&win[1], tid); }
            __syncthreads();
            const int lo = win[0], hi = win[1];
            compute_tin(input, nxt, red, b, dstart, lo, hi, tid);
            float* tsw = cur; cur = nxt; nxt = tsw;
            sup = sup2;
            grid_barrier();  // tin + h published for next phase A
        }
    }
}

extern "C" void kernel_launch(void* const* d_in, const int* in_sizes, int n_in,
                              void* d_out, int out_size) {
    const float* input = (const float*)d_in[0];
    const int*   plen  = (const int*)  d_in[1];
    const float* Wih   = (const float*)d_in[2];
    const float* Whh   = (const float*)d_in[3];
    const float* bih   = (const float*)d_in[4];
    const float* bhh   = (const float*)d_in[5];
    const float* Wsp   = (const float*)d_in[6];
    const float* bsp   = (const float*)d_in[7];
    float* out = (float*)d_out;

    int L = in_sizes[0] / (BB * 512);  // 1000

    cudaFuncSetAttribute(spacing_rnn_kernel,
                         cudaFuncAttributeMaxDynamicSharedMemorySize, SMEM_BYTES);
    spacing_rnn_kernel<<<NBLK, NTHR, SMEM_BYTES>>>(input, plen, Wih, Whh, bih, bhh,
                                                   Wsp, bsp, out, L);
}

// round 12
// speedup vs baseline: 1.5978x; 1.5978x over previous
#include <cuda_runtime.h>
#include <math.h>
#include <stdint.h>

// ---------------- problem constants (fixed shapes) ----------------
#define BB    64      // batch
#define HH    512     // hidden
#define DD    512     // input dim
#define NBLK  128     // persistent blocks; block i owns hidden dims [4i,4i+4)
#define NTHR  1024
#define KTOT  1024    // GEMM K = D + H
#define WST   1032    // SMEM weight row stride (1024 + 8 pad)
#define ATTN_THRESH 1e-10f

// ---------------- SMEM layout (float offsets) ----------------
#define OFF_W     0
#define SZ_W      (16*WST)              // 16512
#define OFF_RED   (OFF_W + SZ_W)
#define SZ_RED    17408                 // 16 kslices * 1088 (tile stride 17)
#define OFF_ATTNA (OFF_RED + SZ_RED)
#define OFF_ATTNB (OFF_ATTNA + 1024)
#define OFF_GATES (OFF_ATTNB + 1024)    // 16 rows x 64 b
#define OFF_C     (OFF_GATES + 1024)    // 256
#define OFF_H2    (OFF_C + 256)         // 256
#define OFF_BS    (OFF_H2 + 256)        // 16
#define OFF_WSP   (OFF_BS + 16)         // 8
#define OFF_BSP   (OFF_WSP + 8)         // 2
#define OFF_SCR   (OFF_BSP + 2)         // 48 reduce scratch
#define OFF_WIN   (OFF_SCR + 48)        // 2 ints
#define SMEM_FLOATS (OFF_WIN + 4)
#define SMEM_BYTES  (SMEM_FLOATS*4)

// ---------------- persistent global state (no allocs allowed) ----------------
__device__ float    g_AT[KTOT * BB];     // [k][b]; k<512 = time_in, k>=512 = h
__device__ float    g_spp[BB * 256];     // sp partials, batch-major [b][g*128+blk]
__device__ unsigned g_cnt;               // barrier count (returns to 0)
__device__ unsigned g_gen;               // barrier generation (monotone)

// ---------------- grid-wide barrier (all 128 blocks co-resident) ----------------
// Release: ALL threads fence (each drains its own global stores) before arrival.
// Acquire: tid0's __threadfence emits CCTL.IVALL (SM-wide L1D invalidate) before
// the closing __syncthreads, so every thread's subsequent loads see fresh L2.
__device__ __forceinline__ void grid_barrier() {
    __syncthreads();
    __threadfence();
    if (threadIdx.x == 0) {
        unsigned gen = *(volatile unsigned*)&g_gen;
        if (atomicAdd(&g_cnt, 1u) == gridDim.x - 1) {
            atomicExch(&g_cnt, 0u);
            __threadfence();
            atomicExch(&g_gen, gen + 1u);
        } else {
            while (*(volatile unsigned*)&g_gen == gen) { __nanosleep(64); }
        }
        __threadfence();   // acquire + SM-wide L1D invalidate (one thread suffices)
    }
    __syncthreads();
}

// ---------------- block reductions (all 1024 threads) ----------------
__device__ __forceinline__ float brsum(float v, float* scr) {
#pragma unroll
    for (int o = 16; o; o >>= 1) v += __shfl_xor_sync(0xffffffffu, v, o);
    __syncthreads();
    if ((threadIdx.x & 31) == 0) scr[threadIdx.x >> 5] = v;
    __syncthreads();
    if (threadIdx.x < 32) {
        float w = scr[threadIdx.x];
#pragma unroll
        for (int o = 16; o; o >>= 1) w += __shfl_xor_sync(0xffffffffu, w, o);
        if (threadIdx.x == 0) scr[0] = w;
    }
    __syncthreads();
    return scr[0];
}

__device__ __forceinline__ float brmax(float v, float* scr) {
#pragma unroll
    for (int o = 16; o; o >>= 1) v = fmaxf(v, __shfl_xor_sync(0xffffffffu, v, o));
    __syncthreads();
    if ((threadIdx.x & 31) == 0) scr[threadIdx.x >> 5] = v;
    __syncthreads();
    if (threadIdx.x < 32) {
        float w = scr[threadIdx.x];
#pragma unroll
        for (int o = 16; o; o >>= 1) w = fmaxf(w, __shfl_xor_sync(0xffffffffu, w, o));
        if (threadIdx.x == 0) scr[0] = w;
    }
    __syncthreads();
    return scr[0];
}

// ---------------- rank-1 register-tile update ----------------
__device__ __forceinline__ void rank1(float acc[4][4], float4 a,
                                      float w0, float w1, float w2, float w3) {
    acc[0][0] = fmaf(a.x, w0, acc[0][0]); acc[0][1] = fmaf(a.x, w1, acc[0][1]);
    acc[0][2] = fmaf(a.x, w2, acc[0][2]); acc[0][3] = fmaf(a.x, w3, acc[0][3]);
    acc[1][0] = fmaf(a.y, w0, acc[1][0]); acc[1][1] = fmaf(a.y, w1, acc[1][1]);
    acc[1][2] = fmaf(a.y, w2, acc[1][2]); acc[1][3] = fmaf(a.y, w3, acc[1][3]);
    acc[2][0] = fmaf(a.z, w0, acc[2][0]); acc[2][1] = fmaf(a.z, w1, acc[2][1]);
    acc[2][2] = fmaf(a.z, w2, acc[2][2]); acc[2][3] = fmaf(a.z, w3, acc[2][3]);
    acc[3][0] = fmaf(a.w, w0, acc[3][0]); acc[3][1] = fmaf(a.w, w1, acc[3][1]);
    acc[3][2] = fmaf(a.w, w2, acc[3][2]); acc[3][3] = fmaf(a.w, w3, acc[3][3]);
}

// ---------------- time_in over attn window; 4 independent accumulators -------
__device__ __forceinline__ void compute_tin(const float* __restrict__ input,
                                            const float* __restrict__ an,
                                            float* tinred, int b, int dstart,
                                            int lo, int hi, int tid) {
    __syncthreads();  // protect tinred region reuse
    const int dloc = tid & 255;
    const int ls   = tid >> 8;       // 0..3
    const float* xp = input + (size_t)b * 512 + dstart + dloc;
    float s0 = 0.f, s1 = 0.f, s2 = 0.f, s3 = 0.f;
    int l = lo + ls;
    for (; l + 12 <= hi; l += 16) {   // 4 loads in flight per thread
        s0 = fmaf(xp[(size_t)(l +  0) * 32768], an[l +  0], s0);
        s1 = fmaf(xp[(size_t)(l +  4) * 32768], an[l +  4], s1);
        s2 = fmaf(xp[(size_t)(l +  8) * 32768], an[l +  8], s2);
        s3 = fmaf(xp[(size_t)(l + 12) * 32768], an[l + 12], s3);
    }
    for (; l <= hi; l += 4)
        s0 = fmaf(xp[(size_t)l * 32768], an[l], s0);
    tinred[ls * 256 + dloc] = (s0 + s1) + (s2 + s3);
    __syncthreads();
    if (tid < 256) {
        float v = tinred[tid] + tinred[256 + tid] + tinred[512 + tid] + tinred[768 + tid];
        g_AT[(dstart + tid) * 64 + b] = v;
    }
}

// ---------------- persistent kernel ----------------
__global__ void __launch_bounds__(NTHR, 1)
spacing_rnn_kernel(const float* __restrict__ input, const int* __restrict__ plen,
                   const float* __restrict__ Wih, const float* __restrict__ Whh,
                   const float* __restrict__ bih, const float* __restrict__ bhh,
                   const float* __restrict__ Wsp, const float* __restrict__ bsp,
                   float* __restrict__ out, int L)
{
    extern __shared__ float sm[];
    float* Wsm   = sm + OFF_W;
    float* red   = sm + OFF_RED;
    float* attnA = sm + OFF_ATTNA;
    float* attnB = sm + OFF_ATTNB;
    float* gates = sm + OFF_GATES;
    float* csm   = sm + OFF_C;
    float* h2s   = sm + OFF_H2;
    float* bsum  = sm + OFF_BS;
    float* wspc  = sm + OFF_WSP;
    float* bspc  = sm + OFF_BSP;
    float* scr   = sm + OFF_SCR;
    int*   win   = (int*)(sm + OFF_WIN);

    const int tid    = threadIdx.x;
    const int bi     = blockIdx.x;
    const int j0     = bi * 4;              // owned hidden dims j0..j0+3
    const int b      = bi & 63;             // batch this block serves in phase B
    const int dstart = (bi >> 6) * 256;     // dim half for time_in
    int len = plen[0];
    if (len <= 0 || len > L) len = L;

    // ---------------- prologue ----------------
    for (int li = tid; li < 16 * 1024; li += NTHR) {
        int r = li >> 10, k = li & 1023;
        int gate = r >> 2, jl = r & 3;
        int grow = gate * 512 + j0 + jl;
        float w = (k < 512) ? Wih[grow * 512 + k] : Whh[grow * 512 + k - 512];
        Wsm[r * WST + k] = w;
    }
    if (tid < 16) {
        int gate = tid >> 2, jl = tid & 3;
        int grow = gate * 512 + j0 + jl;
        bsum[tid] = bih[grow] + bhh[grow];
    }
    if (tid < 8)  wspc[tid] = Wsp[(tid >> 2) * 512 + j0 + (tid & 3)];
    if (tid < 2)  bspc[tid] = bsp[tid];
    attnA[tid] = (tid == 0) ? 1.f : 0.f;
    attnB[tid] = 0.f;
    if (tid < 256) {
        csm[tid] = 0.f;
        g_AT[(512 + j0 + (tid & 3)) * 64 + (tid >> 2)] = 0.f;  // h0 = 0
    }
    __syncthreads();
    compute_tin(input, attnA, red + 1024, b, dstart, 0, 0, tid);  // tin(0) = x[:, :, 0]
    grid_barrier();

    float* cur = attnA;
    float* nxt = attnB;
    int sup = 0;  // attn support is [0, sup]

    for (int t = 0; t < len; t++) {
        // ============ PHASE A: gates GEMM + LSTM cell ============
        {
            const int tile = tid & 63;
            const int ks   = tid >> 6;
            const int b0   = (tile & 15) * 4;
            const int r0   = (tile >> 4) * 4;
            const int k0   = ks * 64;
            float acc[4][4];
#pragma unroll
            for (int i = 0; i < 4; i++)
#pragma unroll
                for (int j = 0; j < 4; j++) acc[i][j] = 0.f;
            const float* Wb = Wsm + r0 * WST;
#pragma unroll 2
            for (int kk = 0; kk < 64; kk += 4) {
                const int k = k0 + kk;
                float4 w0 = *(const float4*)(Wb + 0 * WST + k);
                float4 w1 = *(const float4*)(Wb + 1 * WST + k);
                float4 w2 = *(const float4*)(Wb + 2 * WST + k);
                float4 w3 = *(const float4*)(Wb + 3 * WST + k);
                float4 a0 = *(const float4*)(g_AT + (size_t)(k + 0) * 64 + b0);
                float4 a1 = *(const float4*)(g_AT + (size_t)(k + 1) * 64 + b0);
                float4 a2 = *(const float4*)(g_AT + (size_t)(k + 2) * 64 + b0);
                float4 a3 = *(const float4*)(g_AT + (size_t)(k + 3) * 64 + b0);
                rank1(acc, a0, w0.x, w1.x, w2.x, w3.x);
                rank1(acc, a1, w0.y, w1.y, w2.y, w3.y);
                rank1(acc, a2, w0.z, w1.z, w2.z, w3.z);
                rank1(acc, a3, w0.w, w1.w, w2.w, w3.w);
            }
            __syncthreads();  // red region free (last used as tinred pre-barrier)
            const int base = ks * 1088 + tile * 17;
#pragma unroll
            for (int i = 0; i < 4; i++)
#pragma unroll
                for (int j = 0; j < 4; j++) red[base + i * 4 + j] = acc[i][j];
        }
        __syncthreads();
        {   // gather 16 k-slice partials -> gates[r][b]
            const int tile = tid >> 4, v = tid & 15;
            float s = 0.f;
#pragma unroll
            for (int ks2 = 0; ks2 < 16; ks2++) s += red[ks2 * 1088 + tile * 17 + v];
            const int bb2 = (tile & 15) * 4 + (v >> 2);
            const int rr  = (tile >> 4) * 4 + (v & 3);
            gates[rr * 64 + bb2] = s;
        }
        __syncthreads();
        if (tid < 256) {  // LSTM cell for (b = tid>>2, jl = tid&3)
            const int bb2 = tid >> 2, jl = tid & 3;
            float gi = gates[(0  + jl) * 64 + bb2] + bsum[0  + jl];
            float gf = gates[(4  + jl) * 64 + bb2] + bsum[4  + jl];
            float gg = gates[(8  + jl) * 64 + bb2] + bsum[8  + jl];
            float go = gates[(12 + jl) * 64 + bb2] + bsum[12 + jl];
            float c  = csm[tid];
            float si = 1.f / (1.f + __expf(-gi));
            float sf = 1.f / (1.f + __expf(-gf));
            float so = 1.f / (1.f + __expf(-go));
            float c2 = sf * c + si * tanhf(gg);
            float h2 = so * tanhf(c2);
            csm[tid] = c2;
            h2s[tid] = h2;
            out[(size_t)t * 32768 + (size_t)bb2 * 512 + j0 + jl] = h2;
        }
        __syncthreads();
        if (tid < 128) {  // sp partial (batch-major store for contiguous reload)
            const int g = tid >> 6, bb2 = tid & 63;
            float s = h2s[bb2 * 4 + 0] * wspc[g * 4 + 0] + h2s[bb2 * 4 + 1] * wspc[g * 4 + 1]
                    + h2s[bb2 * 4 + 2] * wspc[g * 4 + 2] + h2s[bb2 * 4 + 3] * wspc[g * 4 + 3];
            g_spp[bb2 * 256 + g * 128 + bi] = s;
        }
        grid_barrier();  // h(t-1) reads done; sp partials visible

        // ============ PHASE B: publish h, attn update, time_in ============
        if (t + 1 < len) {
            if (tid < 256) {  // publish h2 -> g_AT (safe: all GEMM reads done)
                const int bb2 = tid >> 2, jl = tid & 3;
                g_AT[(512 + j0 + jl) * 64 + bb2] = h2s[tid];
            }
            // --- reduce sp over 128 blocks for batch b (contiguous read) ---
            {
                float v = (tid < 256) ? g_spp[b * 256 + tid] : 0.f;
#pragma unroll
                for (int o = 16; o; o >>= 1) v += __shfl_xor_sync(0xffffffffu, v, o);
                if (tid < 256 && (tid & 31) == 0) scr[40 + (tid >> 5)] = v;  // 8 partials
                __syncthreads();
                if (tid == 0) {
                    float sp0 = scr[40] + scr[41] + scr[42] + scr[43];
                    float sp1 = scr[44] + scr[45] + scr[46] + scr[47];
                    scr[36] = 1.f / (1.f + __expf(-(sp0 + bspc[0])));
                    float pp = sp1 + bspc[1];
                    scr[37] = (pp > 0.f ? pp : 0.f) + 1.f;
                }
                __syncthreads();
            }
            const float shift = scr[36];
            const float p     = scr[37];
            const int sup2 = min(sup + 1, L - 1);
            __syncthreads();
            if (tid == 0) { win[0] = 0x7fffffff; win[1] = -1; }
            // --- attn: shift mix (exact, full support) ---
            float a2 = 0.f;
            if (tid <= sup2) {
                float a  = cur[tid];
                float ap = (tid > 0) ? cur[tid - 1] : 0.f;
                a2 = (1.f - shift) * a + shift * ap;
            }
            // --- sharpen + normalize (max-scaled pow; identical after normalize) ---
            float amax  = brmax(a2, scr);
            float lmax  = __logf(amax);
            float powed = (a2 > 0.f) ? __expf(p * (__logf(a2) - lmax)) : 0.f;
            float ssum  = brsum(powed, scr);
            float anew  = powed * (1.f / ssum);
            nxt[tid] = anew;
            if (anew >= ATTN_THRESH) { atomicMin(&win[0], tid); atomicMax(&win[1], tid); }
            __syncthreads();
            const int lo = win[0], hi = win[1];
            // --- time_in(t+1) over the thresholded window ---
            compute_tin(input, nxt, red + 1024, b, dstart, lo, hi, tid);
            float* tsw = cur; cur = nxt; nxt = tsw;
            sup = sup2;
            grid_barrier();  // tin + h published for next phase A
        }
    }
}

extern "C" void kernel_launch(void* const* d_in, const int* in_sizes, int n_in,
                              void* d_out, int out_size) {
    const float* input = (const float*)d_in[0];
    const int*   plen  = (const int*)  d_in[1];
    const float* Wih   = (const float*)d_in[2];
    const float* Whh   = (const float*)d_in[3];
    const float* bih   = (const float*)d_in[4];
    const float* bhh   = (const float*)d_in[5];
    const float* Wsp   = (const float*)d_in[6];
    const float* bsp   = (const float*)d_in[7];
    float* out = (float*)d_out;

    int L = in_sizes[0] / (BB * DD);  // 1000

    cudaFuncSetAttribute(spacing_rnn_kernel,
                         cudaFuncAttributeMaxDynamicSharedMemorySize, SMEM_BYTES);
    spacing_rnn_kernel<<<NBLK, NTHR, SMEM_BYTES>>>(input, plen, Wih, Whh, bih, bhh,
                                                   Wsp, bsp, out, L);
}